// round 4
// baseline (speedup 1.0000x reference)
#include <cuda_runtime.h>
#include <math.h>
#include <stdint.h>

// ---------------- problem constants ----------------
#define D_MODEL 256
#define D_FFN   1024
#define LQ      21760
#define BATCH   2
#define M_ROWS  (BATCH * LQ)   // 43520

__device__ __constant__ int c_H[4]  = {128, 64, 32, 16};
__device__ __constant__ int c_W[4]  = {128, 64, 32, 16};
__device__ __constant__ int c_ST[4] = {0, 16384, 20480, 21504};

// ---------------- scratch ----------------
__device__ float g_src32[(size_t)M_ROWS * D_MODEL];
__device__ float g_qsum [(size_t)M_ROWS * D_MODEL];
__device__ float g_value[(size_t)M_ROWS * D_MODEL];
__device__ float g_oa   [(size_t)M_ROWS * 384];     // offs (256) | attn logits (128)
__device__ float g_samp [(size_t)M_ROWS * D_MODEL];
__device__ float g_t1   [(size_t)M_ROWS * D_MODEL];
__device__ float g_h    [(size_t)M_ROWS * D_MODEL];
__device__ float g_h32  [(size_t)M_ROWS * D_MODEL];
__device__ float g_ffn  [(size_t)M_ROWS * D_FFN];
__device__ float g_t2   [(size_t)M_ROWS * D_MODEL];
__device__ float g_WvalT [256 * 256];
__device__ float g_WoaT  [384 * 256];               // rows 0..255 WoffT, 256..383 WattnT
__device__ float g_WoutT [256 * 256];
__device__ float g_W1T   [1024 * 256];
__device__ float g_W2T   [256 * 1024];

// ---------------- helpers ----------------
__device__ __forceinline__ uint32_t smem_u32(const void* p) {
    uint32_t a;
    asm("{ .reg .u64 t; cvta.to.shared.u64 t, %1; cvt.u32.u64 %0, t; }" : "=r"(a) : "l"(p));
    return a;
}
__device__ __forceinline__ float rna_tf32(float x) {
    uint32_t u;
    asm("cvt.rna.tf32.f32 %0, %1;" : "=r"(u) : "f"(x));
    return __uint_as_float(u);
}
__device__ __forceinline__ void cpasync16(uint32_t dst, const void* src) {
    asm volatile("cp.async.cg.shared.global [%0], [%1], 16;" :: "r"(dst), "l"(src));
}
__device__ __forceinline__ void ldsm_x4(uint32_t& r0, uint32_t& r1, uint32_t& r2, uint32_t& r3, uint32_t addr) {
    asm volatile("ldmatrix.sync.aligned.m8n8.x4.shared.b16 {%0,%1,%2,%3}, [%4];"
        : "=r"(r0), "=r"(r1), "=r"(r2), "=r"(r3) : "r"(addr));
}
__device__ __forceinline__ void mma_tf32(float* d, const uint32_t* a, const uint32_t* b) {
    asm volatile("mma.sync.aligned.m16n8k8.row.col.f32.tf32.tf32.f32 "
        "{%0,%1,%2,%3}, {%4,%5,%6,%7}, {%8,%9}, {%0,%1,%2,%3};"
        : "+f"(d[0]), "+f"(d[1]), "+f"(d[2]), "+f"(d[3])
        : "r"(a[0]), "r"(a[1]), "r"(a[2]), "r"(a[3]), "r"(b[0]), "r"(b[1]));
}

// ---------------- tensor-core tf32 GEMM via mma.sync ----------------
// C[M,N] = A[M,K] @ W[K,N] + bias (+res) (relu) (round). bias split at nsplit -> bias2.
template <bool RESF, bool RELUF, bool ROUNDF>
__global__ void __launch_bounds__(256) gemm_mma(
    const float* __restrict__ A, const float* __restrict__ WT,
    const float* __restrict__ bias, const float* __restrict__ bias2, int nsplit,
    const float* __restrict__ res, float* __restrict__ C, int N, int K)
{
    extern __shared__ char dynsm[];
    const uint32_t smBase = smem_u32(dynsm);
    const uint32_t smA0 = smBase;               // stage stride 32KB
    const uint32_t smB0 = smBase + 16384;

    const int tid = threadIdx.x;
    const int lane = tid & 31;
    const int wid = tid >> 5;
    const int wm = wid & 1;
    const int wn = wid >> 1;
    const int bm = blockIdx.y * 128;
    const int bn = blockIdx.x * 128;

    const float* aG[4]; const float* bG[4];
    uint32_t sOff[4];
#pragma unroll
    for (int i = 0; i < 4; i++) {
        const int id = tid + i * 256;
        const int row = id >> 3, ck = id & 7;
        aG[i] = A  + (size_t)(bm + row) * K + ck * 4;
        bG[i] = WT + (size_t)(bn + row) * K + ck * 4;
        sOff[i] = row * 128 + ((ck ^ (row & 7)) * 16);
    }

    const int lt = lane >> 3;
    const int lr = lane & 7;
    const int aRow = wm * 64 + (lt & 1) * 8 + lr;
    const int aCk0 = (lt >> 1);
    const int bRow = wn * 32 + (lt >> 1) * 8 + lr;
    const int bCk0 = (lt & 1);

    float acc[4][4][4];
#pragma unroll
    for (int i = 0; i < 4; i++)
#pragma unroll
        for (int j = 0; j < 4; j++)
#pragma unroll
            for (int k = 0; k < 4; k++) acc[i][j][k] = 0.f;

    const int Cs = K >> 5;

#pragma unroll
    for (int i = 0; i < 4; i++) {
        cpasync16(smA0 + sOff[i], aG[i]);
        cpasync16(smB0 + sOff[i], bG[i]);
    }
    asm volatile("cp.async.commit_group;" ::: "memory");
#pragma unroll
    for (int i = 0; i < 4; i++) {
        cpasync16(smA0 + 32768 + sOff[i], aG[i] + 32);
        cpasync16(smB0 + 32768 + sOff[i], bG[i] + 32);
    }
    asm volatile("cp.async.commit_group;" ::: "memory");

    for (int c = 0; c < Cs; ++c) {
        const int st = c & 1;
        const uint32_t sA = smA0 + st * 32768;
        const uint32_t sB = smB0 + st * 32768;
        if (c == Cs - 1) asm volatile("cp.async.wait_group 0;" ::: "memory");
        else             asm volatile("cp.async.wait_group 1;" ::: "memory");
        __syncthreads();

#pragma unroll
        for (int ks = 0; ks < 4; ks++) {
            uint32_t af[4][4];
            uint32_t bf[4][2];
#pragma unroll
            for (int mt = 0; mt < 4; mt++) {
                const int row = aRow + mt * 16;
                const int ck = aCk0 + ks * 2;
                ldsm_x4(af[mt][0], af[mt][1], af[mt][2], af[mt][3],
                        sA + row * 128 + ((ck ^ (row & 7)) * 16));
            }
#pragma unroll
            for (int np = 0; np < 2; np++) {
                const int row = bRow + np * 16;
                const int ck = bCk0 + ks * 2;
                uint32_t r0, r1, r2, r3;
                ldsm_x4(r0, r1, r2, r3,
                        sB + row * 128 + ((ck ^ (row & 7)) * 16));
                bf[np * 2 + 0][0] = r0; bf[np * 2 + 0][1] = r1;
                bf[np * 2 + 1][0] = r2; bf[np * 2 + 1][1] = r3;
            }
#pragma unroll
            for (int mt = 0; mt < 4; mt++)
#pragma unroll
                for (int nt = 0; nt < 4; nt++)
                    mma_tf32(acc[mt][nt], af[mt], bf[nt]);
        }
        __syncthreads();

        if (c + 2 < Cs) {
            const int k0 = (c + 2) << 5;
#pragma unroll
            for (int i = 0; i < 4; i++) {
                cpasync16(sA + sOff[i], aG[i] + k0);
                cpasync16(sB + sOff[i], bG[i] + k0);
            }
            asm volatile("cp.async.commit_group;" ::: "memory");
        }
    }

    const int r0base = bm + wm * 64 + (lane >> 2);
    const int cbase  = bn + wn * 32 + (lane & 3) * 2;
#pragma unroll
    for (int mt = 0; mt < 4; mt++) {
#pragma unroll
        for (int nt = 0; nt < 4; nt++) {
            const int col = cbase + nt * 8;
            const float bx = (col < nsplit) ? bias[col] : bias2[col - nsplit];
            const float by = (col + 1 < nsplit) ? bias[col + 1] : bias2[col + 1 - nsplit];
#pragma unroll
            for (int half = 0; half < 2; half++) {
                const int row = r0base + mt * 16 + half * 8;
                float vx = acc[mt][nt][half * 2 + 0] + bx;
                float vy = acc[mt][nt][half * 2 + 1] + by;
                if (RESF) {
                    const float* rp = res + (size_t)row * N + col;
                    vx += rp[0]; vy += rp[1];
                }
                if (RELUF) { vx = fmaxf(vx, 0.f); vy = fmaxf(vy, 0.f); }
                if (ROUNDF) { vx = rna_tf32(vx); vy = rna_tf32(vy); }
                *(float2*)(C + (size_t)row * N + col) = make_float2(vx, vy);
            }
        }
    }
}

// ---------------- prep: rounded src, rounded (src+pos) ----------------
__global__ void __launch_bounds__(256) prep_kernel(
    const float* __restrict__ src, const float* __restrict__ pos,
    float* __restrict__ src32, float* __restrict__ qsum, int n4)
{
    int i = blockIdx.x * blockDim.x + threadIdx.x;
    if (i >= n4) return;
    float4 s = ((const float4*)src)[i];
    float4 p = ((const float4*)pos)[i];
    float4 a, q;
    a.x = rna_tf32(s.x); a.y = rna_tf32(s.y); a.z = rna_tf32(s.z); a.w = rna_tf32(s.w);
    q.x = rna_tf32(s.x + p.x); q.y = rna_tf32(s.y + p.y);
    q.z = rna_tf32(s.z + p.z); q.w = rna_tf32(s.w + p.w);
    ((float4*)src32)[i] = a;
    ((float4*)qsum)[i] = q;
}

// ---------------- weight transpose + tf32 rounding ----------------
__global__ void __launch_bounds__(256) transpose_rna(
    const float* __restrict__ W, float* __restrict__ WT, int K, int N)
{
    __shared__ float tile[32][33];
    const int k0 = blockIdx.y * 32, n0 = blockIdx.x * 32;
    const int tx = threadIdx.x & 31, ty = threadIdx.x >> 5;
#pragma unroll
    for (int r = 0; r < 4; r++)
        tile[ty + r * 8][tx] = W[(size_t)(k0 + ty + r * 8) * N + n0 + tx];
    __syncthreads();
#pragma unroll
    for (int r = 0; r < 4; r++)
        WT[(size_t)(n0 + ty + r * 8) * K + k0 + tx] = rna_tf32(tile[tx][ty + r * 8]);
}

// ---------------- deformable sampling: 8-lane group per (bq, head), float4 channels --
__global__ void __launch_bounds__(256) sample_kernel4(
    const float* __restrict__ value,   // [B*LQ, 8, 32]
    const float* __restrict__ oa,      // [B*LQ, 384]: offs 0..255, logits 256..383
    const float* __restrict__ refp,    // [B*LQ, 4, 2]
    float* __restrict__ samp)          // [B*LQ, 256]
{
    const int lane = threadIdx.x & 31;
    const int li = lane & 7;
    const int pair = blockIdx.x * 32 + (threadIdx.x >> 3);
    const int h  = pair & 7;
    const int bq = pair >> 3;
    const int b  = bq / LQ;

    // softmax over 16 logits within the 8-lane group
    const float* aBase = oa + (size_t)bq * 384 + 256 + h * 16;
    const float l0 = aBase[li], l1 = aBase[li + 8];
    float mx = fmaxf(l0, l1);
#pragma unroll
    for (int o = 4; o; o >>= 1) mx = fmaxf(mx, __shfl_xor_sync(0xffffffffu, mx, o));
    const float e0 = __expf(l0 - mx), e1 = __expf(l1 - mx);
    float se = e0 + e1;
#pragma unroll
    for (int o = 4; o; o >>= 1) se += __shfl_xor_sync(0xffffffffu, se, o);
    const float inv_se = 1.f / se;

    const float* op = oa + (size_t)bq * 384 + h * 32;
    const float* rp = refp + (size_t)bq * 8;
    const float4* v4 = (const float4*)value + (size_t)b * LQ * 64 + h * 8 + li;

    float4 acc = make_float4(0.f, 0.f, 0.f, 0.f);
#pragma unroll
    for (int lvl = 0; lvl < 4; lvl++) {
        const int Hh = c_H[lvl], Ww = c_W[lvl], st = c_ST[lvl];
        const float invW = 1.f / (float)Ww, invH = 1.f / (float)Hh;
        const float rx = rp[lvl * 2 + 0];
        const float ry = rp[lvl * 2 + 1];
        const float4* vb = v4 + (size_t)st * 64;
#pragma unroll
        for (int p = 0; p < 4; p++) {
            const int idx = lvl * 4 + p;
            const float ox = op[lvl * 8 + p * 2 + 0];
            const float oy = op[lvl * 8 + p * 2 + 1];
            const float x = (rx + ox * invW) * (float)Ww - 0.5f;
            const float y = (ry + oy * invH) * (float)Hh - 0.5f;
            const float w = __shfl_sync(0xffffffffu, (idx < 8) ? e0 : e1,
                                        (lane & 24) | (idx & 7)) * inv_se;

            const float x0f = floorf(x), y0f = floorf(y);
            const int x0 = (int)x0f, y0 = (int)y0f;
            const float wx1 = x - x0f, wy1 = y - y0f;
            const float wx0 = 1.f - wx1, wy0 = 1.f - wy1;

            const bool xv0 = (x0 >= 0) && (x0 < Ww);
            const bool xv1 = (x0 + 1 >= 0) && (x0 + 1 < Ww);
            const bool yv0 = (y0 >= 0) && (y0 < Hh);
            const bool yv1 = (y0 + 1 >= 0) && (y0 + 1 < Hh);

            float4 v00 = make_float4(0.f,0.f,0.f,0.f), v10 = v00, v01 = v00, v11 = v00;
            if (yv0) {
                const int base = (y0 * Ww) * 64;
                if (xv0) v00 = vb[base + x0 * 64];
                if (xv1) v10 = vb[base + (x0 + 1) * 64];
            }
            if (yv1) {
                const int base = ((y0 + 1) * Ww) * 64;
                if (xv0) v01 = vb[base + x0 * 64];
                if (xv1) v11 = vb[base + (x0 + 1) * 64];
            }
            const float w00 = wx0 * wy0, w10 = wx1 * wy0;
            const float w01 = wx0 * wy1, w11 = wx1 * wy1;
            acc.x += w * (w00 * v00.x + w10 * v10.x + w01 * v01.x + w11 * v11.x);
            acc.y += w * (w00 * v00.y + w10 * v10.y + w01 * v01.y + w11 * v11.y);
            acc.z += w * (w00 * v00.z + w10 * v10.z + w01 * v01.z + w11 * v11.z);
            acc.w += w * (w00 * v00.w + w10 * v10.w + w01 * v01.w + w11 * v11.w);
        }
    }
    float4 o4;
    o4.x = rna_tf32(acc.x); o4.y = rna_tf32(acc.y);
    o4.z = rna_tf32(acc.z); o4.w = rna_tf32(acc.w);
    ((float4*)(samp + (size_t)bq * 256 + h * 32))[li] = o4;
}

// ---------------- layernorm: one warp per row, float4 ----------------
template <bool WR32>
__global__ void __launch_bounds__(256) ln4_kernel(
    const float* __restrict__ in, const float* __restrict__ g,
    const float* __restrict__ b, float* __restrict__ out, float* __restrict__ out32)
{
    const int lane = threadIdx.x & 31;
    const size_t row = blockIdx.x * 8 + (threadIdx.x >> 5);
    const float4* in4 = (const float4*)(in + row * 256);
    const float4 A = in4[lane * 2], B4 = in4[lane * 2 + 1];

    float s = A.x + A.y + A.z + A.w + B4.x + B4.y + B4.z + B4.w;
#pragma unroll
    for (int o = 16; o; o >>= 1) s += __shfl_xor_sync(0xffffffffu, s, o);
    const float mu = s * (1.f / 256.f);

    float4 dA, dB;
    dA.x = A.x - mu; dA.y = A.y - mu; dA.z = A.z - mu; dA.w = A.w - mu;
    dB.x = B4.x - mu; dB.y = B4.y - mu; dB.z = B4.z - mu; dB.w = B4.w - mu;
    float v = dA.x*dA.x + dA.y*dA.y + dA.z*dA.z + dA.w*dA.w
            + dB.x*dB.x + dB.y*dB.y + dB.z*dB.z + dB.w*dB.w;
#pragma unroll
    for (int o = 16; o; o >>= 1) v += __shfl_xor_sync(0xffffffffu, v, o);
    const float rstd = rsqrtf(v * (1.f / 256.f) + 1e-5f);

    const float4 gA = ((const float4*)g)[lane * 2], gB = ((const float4*)g)[lane * 2 + 1];
    const float4 bA = ((const float4*)b)[lane * 2], bB = ((const float4*)b)[lane * 2 + 1];
    float4 yA, yB;
    yA.x = dA.x * rstd * gA.x + bA.x; yA.y = dA.y * rstd * gA.y + bA.y;
    yA.z = dA.z * rstd * gA.z + bA.z; yA.w = dA.w * rstd * gA.w + bA.w;
    yB.x = dB.x * rstd * gB.x + bB.x; yB.y = dB.y * rstd * gB.y + bB.y;
    yB.z = dB.z * rstd * gB.z + bB.z; yB.w = dB.w * rstd * gB.w + bB.w;

    float4* o4 = (float4*)(out + row * 256);
    o4[lane * 2] = yA; o4[lane * 2 + 1] = yB;
    if (WR32) {
        float4 rA, rB;
        rA.x = rna_tf32(yA.x); rA.y = rna_tf32(yA.y); rA.z = rna_tf32(yA.z); rA.w = rna_tf32(yA.w);
        rB.x = rna_tf32(yB.x); rB.y = rna_tf32(yB.y); rB.z = rna_tf32(yB.z); rB.w = rna_tf32(yB.w);
        float4* r4 = (float4*)(out32 + row * 256);
        r4[lane * 2] = rA; r4[lane * 2 + 1] = rB;
    }
}

// ---------------- launch ----------------
extern "C" void kernel_launch(void* const* d_in, const int* in_sizes, int n_in,
                              void* d_out, int out_size)
{
    const float* src    = (const float*)d_in[0];
    const float* pos    = (const float*)d_in[1];
    const float* refp   = (const float*)d_in[2];
    const float* W_off  = (const float*)d_in[3];
    const float* b_off  = (const float*)d_in[4];
    const float* W_attn = (const float*)d_in[5];
    const float* b_attn = (const float*)d_in[6];
    const float* W_val  = (const float*)d_in[7];
    const float* b_val  = (const float*)d_in[8];
    const float* W_out  = (const float*)d_in[9];
    const float* b_out  = (const float*)d_in[10];
    const float* ln1_g  = (const float*)d_in[11];
    const float* ln1_b  = (const float*)d_in[12];
    const float* W1     = (const float*)d_in[13];
    const float* b1     = (const float*)d_in[14];
    const float* W2     = (const float*)d_in[15];
    const float* b2     = (const float*)d_in[16];
    const float* ln2_g  = (const float*)d_in[17];
    const float* ln2_b  = (const float*)d_in[18];
    float* out = (float*)d_out;

    float *p_src32, *p_qsum, *p_value, *p_oa, *p_samp, *p_t1, *p_h, *p_h32, *p_ffn, *p_t2;
    float *p_WvalT, *p_WoaT, *p_WoutT, *p_W1T, *p_W2T;
    cudaGetSymbolAddress((void**)&p_src32, g_src32);
    cudaGetSymbolAddress((void**)&p_qsum,  g_qsum);
    cudaGetSymbolAddress((void**)&p_value, g_value);
    cudaGetSymbolAddress((void**)&p_oa,    g_oa);
    cudaGetSymbolAddress((void**)&p_samp,  g_samp);
    cudaGetSymbolAddress((void**)&p_t1,    g_t1);
    cudaGetSymbolAddress((void**)&p_h,     g_h);
    cudaGetSymbolAddress((void**)&p_h32,   g_h32);
    cudaGetSymbolAddress((void**)&p_ffn,   g_ffn);
    cudaGetSymbolAddress((void**)&p_t2,    g_t2);
    cudaGetSymbolAddress((void**)&p_WvalT, g_WvalT);
    cudaGetSymbolAddress((void**)&p_WoaT,  g_WoaT);
    cudaGetSymbolAddress((void**)&p_WoutT, g_WoutT);
    cudaGetSymbolAddress((void**)&p_W1T,   g_W1T);
    cudaGetSymbolAddress((void**)&p_W2T,   g_W2T);

    const int SMEM_BYTES = 2 * 32768;
    cudaFuncSetAttribute(gemm_mma<false, false, false>, cudaFuncAttributeMaxDynamicSharedMemorySize, SMEM_BYTES);
    cudaFuncSetAttribute(gemm_mma<true,  false, false>, cudaFuncAttributeMaxDynamicSharedMemorySize, SMEM_BYTES);
    cudaFuncSetAttribute(gemm_mma<false, true,  true >, cudaFuncAttributeMaxDynamicSharedMemorySize, SMEM_BYTES);

    const int M = M_ROWS;
    const int MT = M / 128;  // 340
    const int BIG = 1 << 30;

    // prep
    {
        int n4 = M * D_MODEL / 4;
        prep_kernel<<<(n4 + 255) / 256, 256>>>(src, pos, p_src32, p_qsum, n4);
    }
    // weight transposes (rounded to tf32)
    transpose_rna<<<dim3(8, 8), 256>>>(W_val,  p_WvalT, 256, 256);
    transpose_rna<<<dim3(8, 8), 256>>>(W_off,  p_WoaT,  256, 256);
    transpose_rna<<<dim3(4, 8), 256>>>(W_attn, p_WoaT + 256 * 256, 256, 128);
    transpose_rna<<<dim3(8, 8), 256>>>(W_out,  p_WoutT, 256, 256);
    transpose_rna<<<dim3(32, 8), 256>>>(W1,    p_W1T,   256, 1024);
    transpose_rna<<<dim3(8, 32), 256>>>(W2,    p_W2T,   1024, 256);

    // value = src @ W_val + b_val
    gemm_mma<false, false, false><<<dim3(2, MT), 256, SMEM_BYTES>>>(
        p_src32, p_WvalT, b_val, b_val, BIG, nullptr, p_value, 256, 256);
    // oa = (src+pos) @ [W_off|W_attn] + [b_off|b_attn]
    gemm_mma<false, false, false><<<dim3(3, MT), 256, SMEM_BYTES>>>(
        p_qsum, p_WoaT, b_off, b_attn, 256, nullptr, p_oa, 384, 256);
    // sampling (8-lane groups, float4)
    sample_kernel4<<<M * 8 / 32, 256>>>(p_value, p_oa, refp, p_samp);
    // t1 = samp @ W_out + b_out + src
    gemm_mma<true, false, false><<<dim3(2, MT), 256, SMEM_BYTES>>>(
        p_samp, p_WoutT, b_out, b_out, BIG, src, p_t1, 256, 256);
    // h = LN1(t1) (+ rounded copy)
    ln4_kernel<true><<<M / 8, 256>>>(p_t1, ln1_g, ln1_b, p_h, p_h32);
    // ffn = round(relu(h @ W1 + b1))
    gemm_mma<false, true, true><<<dim3(8, MT), 256, SMEM_BYTES>>>(
        p_h32, p_W1T, b1, b1, BIG, nullptr, p_ffn, 1024, 256);
    // t2 = ffn @ W2 + b2 + h
    gemm_mma<true, false, false><<<dim3(2, MT), 256, SMEM_BYTES>>>(
        p_ffn, p_W2T, b2, b2, BIG, p_h, p_t2, 256, 1024);
    // out = LN2(t2)
    ln4_kernel<false><<<M / 8, 256>>>(p_t2, ln2_g, ln2_b, out, nullptr);
}

// round 5
// speedup vs baseline: 1.2997x; 1.2997x over previous
#include <cuda_runtime.h>
#include <math.h>
#include <stdint.h>

// ---------------- problem constants ----------------
#define D_MODEL 256
#define D_FFN   1024
#define LQ      21760
#define BATCH   2
#define M_ROWS  (BATCH * LQ)   // 43520

__device__ __constant__ int c_ST[4] = {0, 16384, 20480, 21504};

// ---------------- scratch ----------------
__device__ float g_src32[(size_t)M_ROWS * D_MODEL];
__device__ float g_qsum [(size_t)M_ROWS * D_MODEL];
__device__ float g_value[(size_t)M_ROWS * D_MODEL];
__device__ float g_oa   [(size_t)M_ROWS * 384];     // offs (256) | attn logits (128)
__device__ float g_samp [(size_t)M_ROWS * D_MODEL];
__device__ float g_t1   [(size_t)M_ROWS * D_MODEL];
__device__ float g_h    [(size_t)M_ROWS * D_MODEL];
__device__ float g_h32  [(size_t)M_ROWS * D_MODEL];
__device__ float g_ffn  [(size_t)M_ROWS * D_FFN];
__device__ float g_t2   [(size_t)M_ROWS * D_MODEL];
__device__ float g_WvalT [256 * 256];
__device__ float g_WoaT  [384 * 256];
__device__ float g_WoutT [256 * 256];
__device__ float g_W1T   [1024 * 256];
__device__ float g_W2T   [256 * 1024];

// ---------------- helpers ----------------
__device__ __forceinline__ uint32_t smem_u32(const void* p) {
    uint32_t a;
    asm("{ .reg .u64 t; cvta.to.shared.u64 t, %1; cvt.u32.u64 %0, t; }" : "=r"(a) : "l"(p));
    return a;
}
__device__ __forceinline__ float rna_tf32(float x) {
    uint32_t u;
    asm("cvt.rna.tf32.f32 %0, %1;" : "=r"(u) : "f"(x));
    return __uint_as_float(u);
}
__device__ __forceinline__ void cpasync16(uint32_t dst, const void* src) {
    asm volatile("cp.async.cg.shared.global [%0], [%1], 16;" :: "r"(dst), "l"(src));
}
__device__ __forceinline__ void ldsm_x4(uint32_t& r0, uint32_t& r1, uint32_t& r2, uint32_t& r3, uint32_t addr) {
    asm volatile("ldmatrix.sync.aligned.m8n8.x4.shared.b16 {%0,%1,%2,%3}, [%4];"
        : "=r"(r0), "=r"(r1), "=r"(r2), "=r"(r3) : "r"(addr));
}
__device__ __forceinline__ void mma_tf32(float* d, const uint32_t* a, const uint32_t* b) {
    asm volatile("mma.sync.aligned.m16n8k8.row.col.f32.tf32.tf32.f32 "
        "{%0,%1,%2,%3}, {%4,%5,%6,%7}, {%8,%9}, {%0,%1,%2,%3};"
        : "+f"(d[0]), "+f"(d[1]), "+f"(d[2]), "+f"(d[3])
        : "r"(a[0]), "r"(a[1]), "r"(a[2]), "r"(a[3]), "r"(b[0]), "r"(b[1]));
}

// ---------------- tensor-core tf32 GEMM via mma.sync ----------------
template <bool RESF, bool RELUF, bool ROUNDF>
__global__ void __launch_bounds__(256) gemm_mma(
    const float* __restrict__ A, const float* __restrict__ WT,
    const float* __restrict__ bias, const float* __restrict__ bias2, int nsplit,
    const float* __restrict__ res, float* __restrict__ C, int N, int K)
{
    extern __shared__ char dynsm[];
    const uint32_t smBase = smem_u32(dynsm);
    const uint32_t smA0 = smBase;
    const uint32_t smB0 = smBase + 16384;

    const int tid = threadIdx.x;
    const int lane = tid & 31;
    const int wid = tid >> 5;
    const int wm = wid & 1;
    const int wn = wid >> 1;
    const int bm = blockIdx.y * 128;
    const int bn = blockIdx.x * 128;

    const float* aG[4]; const float* bG[4];
    uint32_t sOff[4];
#pragma unroll
    for (int i = 0; i < 4; i++) {
        const int id = tid + i * 256;
        const int row = id >> 3, ck = id & 7;
        aG[i] = A  + (size_t)(bm + row) * K + ck * 4;
        bG[i] = WT + (size_t)(bn + row) * K + ck * 4;
        sOff[i] = row * 128 + ((ck ^ (row & 7)) * 16);
    }

    const int lt = lane >> 3;
    const int lr = lane & 7;
    const int aRow = wm * 64 + (lt & 1) * 8 + lr;
    const int aCk0 = (lt >> 1);
    const int bRow = wn * 32 + (lt >> 1) * 8 + lr;
    const int bCk0 = (lt & 1);

    float acc[4][4][4];
#pragma unroll
    for (int i = 0; i < 4; i++)
#pragma unroll
        for (int j = 0; j < 4; j++)
#pragma unroll
            for (int k = 0; k < 4; k++) acc[i][j][k] = 0.f;

    const int Cs = K >> 5;

#pragma unroll
    for (int i = 0; i < 4; i++) {
        cpasync16(smA0 + sOff[i], aG[i]);
        cpasync16(smB0 + sOff[i], bG[i]);
    }
    asm volatile("cp.async.commit_group;" ::: "memory");
#pragma unroll
    for (int i = 0; i < 4; i++) {
        cpasync16(smA0 + 32768 + sOff[i], aG[i] + 32);
        cpasync16(smB0 + 32768 + sOff[i], bG[i] + 32);
    }
    asm volatile("cp.async.commit_group;" ::: "memory");

    for (int c = 0; c < Cs; ++c) {
        const int st = c & 1;
        const uint32_t sA = smA0 + st * 32768;
        const uint32_t sB = smB0 + st * 32768;
        if (c == Cs - 1) asm volatile("cp.async.wait_group 0;" ::: "memory");
        else             asm volatile("cp.async.wait_group 1;" ::: "memory");
        __syncthreads();

#pragma unroll
        for (int ks = 0; ks < 4; ks++) {
            uint32_t af[4][4];
            uint32_t bf[4][2];
#pragma unroll
            for (int mt = 0; mt < 4; mt++) {
                const int row = aRow + mt * 16;
                const int ck = aCk0 + ks * 2;
                ldsm_x4(af[mt][0], af[mt][1], af[mt][2], af[mt][3],
                        sA + row * 128 + ((ck ^ (row & 7)) * 16));
            }
#pragma unroll
            for (int np = 0; np < 2; np++) {
                const int row = bRow + np * 16;
                const int ck = bCk0 + ks * 2;
                uint32_t r0, r1, r2, r3;
                ldsm_x4(r0, r1, r2, r3,
                        sB + row * 128 + ((ck ^ (row & 7)) * 16));
                bf[np * 2 + 0][0] = r0; bf[np * 2 + 0][1] = r1;
                bf[np * 2 + 1][0] = r2; bf[np * 2 + 1][1] = r3;
            }
#pragma unroll
            for (int mt = 0; mt < 4; mt++)
#pragma unroll
                for (int nt = 0; nt < 4; nt++)
                    mma_tf32(acc[mt][nt], af[mt], bf[nt]);
        }
        __syncthreads();

        if (c + 2 < Cs) {
            const int k0 = (c + 2) << 5;
#pragma unroll
            for (int i = 0; i < 4; i++) {
                cpasync16(sA + sOff[i], aG[i] + k0);
                cpasync16(sB + sOff[i], bG[i] + k0);
            }
            asm volatile("cp.async.commit_group;" ::: "memory");
        }
    }

    const int r0base = bm + wm * 64 + (lane >> 2);
    const int cbase  = bn + wn * 32 + (lane & 3) * 2;
#pragma unroll
    for (int mt = 0; mt < 4; mt++) {
#pragma unroll
        for (int nt = 0; nt < 4; nt++) {
            const int col = cbase + nt * 8;
            const float bx = (col < nsplit) ? bias[col] : bias2[col - nsplit];
            const float by = (col + 1 < nsplit) ? bias[col + 1] : bias2[col + 1 - nsplit];
#pragma unroll
            for (int half = 0; half < 2; half++) {
                const int row = r0base + mt * 16 + half * 8;
                float vx = acc[mt][nt][half * 2 + 0] + bx;
                float vy = acc[mt][nt][half * 2 + 1] + by;
                if (RESF) {
                    const float* rp = res + (size_t)row * N + col;
                    vx += rp[0]; vy += rp[1];
                }
                if (RELUF) { vx = fmaxf(vx, 0.f); vy = fmaxf(vy, 0.f); }
                if (ROUNDF) { vx = rna_tf32(vx); vy = rna_tf32(vy); }
                *(float2*)(C + (size_t)row * N + col) = make_float2(vx, vy);
            }
        }
    }
}

// ---------------- prep ----------------
__global__ void __launch_bounds__(256) prep_kernel(
    const float* __restrict__ src, const float* __restrict__ pos,
    float* __restrict__ src32, float* __restrict__ qsum, int n4)
{
    int i = blockIdx.x * blockDim.x + threadIdx.x;
    if (i >= n4) return;
    float4 s = ((const float4*)src)[i];
    float4 p = ((const float4*)pos)[i];
    float4 a, q;
    a.x = rna_tf32(s.x); a.y = rna_tf32(s.y); a.z = rna_tf32(s.z); a.w = rna_tf32(s.w);
    q.x = rna_tf32(s.x + p.x); q.y = rna_tf32(s.y + p.y);
    q.z = rna_tf32(s.z + p.z); q.w = rna_tf32(s.w + p.w);
    ((float4*)src32)[i] = a;
    ((float4*)qsum)[i] = q;
}

// ---------------- weight transpose + tf32 rounding ----------------
__global__ void __launch_bounds__(256) transpose_rna(
    const float* __restrict__ W, float* __restrict__ WT, int K, int N)
{
    __shared__ float tile[32][33];
    const int k0 = blockIdx.y * 32, n0 = blockIdx.x * 32;
    const int tx = threadIdx.x & 31, ty = threadIdx.x >> 5;
#pragma unroll
    for (int r = 0; r < 4; r++)
        tile[ty + r * 8][tx] = W[(size_t)(k0 + ty + r * 8) * N + n0 + tx];
    __syncthreads();
#pragma unroll
    for (int r = 0; r < 4; r++)
        WT[(size_t)(n0 + ty + r * 8) * K + k0 + tx] = rna_tf32(tile[tx][ty + r * 8]);
}

// ---------------- sampler: warp per (bq,h); branch-free, param-lane precompute ------
__global__ void __launch_bounds__(256) sample_bf(
    const float* __restrict__ value,   // [B*LQ, 8, 32]
    const float* __restrict__ oa,      // [B*LQ, 384]
    const float* __restrict__ refp,    // [B*LQ, 4, 2]
    float* __restrict__ samp)          // [B*LQ, 256]
{
    const int warp_id = (blockIdx.x * blockDim.x + threadIdx.x) >> 5;
    const int lane = threadIdx.x & 31;
    const int h  = warp_id & 7;
    const int bq = warp_id >> 3;
    const int b  = (bq >= LQ) ? 1 : 0;

    // ---- softmax over 16 logits (lanes 0..15) ----
    const float* al = oa + (size_t)bq * 384 + 256 + h * 16;
    float logit = (lane < 16) ? al[lane] : -1e30f;
    float mx = logit;
#pragma unroll
    for (int o = 16; o; o >>= 1) mx = fmaxf(mx, __shfl_xor_sync(0xffffffffu, mx, o));
    float e = (lane < 16) ? __expf(logit - mx) : 0.f;
    float se = e;
#pragma unroll
    for (int o = 16; o; o >>= 1) se += __shfl_xor_sync(0xffffffffu, se, o);
    const float inv_se = 1.f / se;

    // ---- per-point params: lane p (0..15) computes point p ----
    float cw0, cw1, cw2, cw3;
    int ci0, ci1, ci2, ci3;
    {
        const int idx = lane & 15;
        const int lvl = idx >> 2;
        const int Ww = 128 >> lvl;            // == H
        const float fW = (float)Ww;
        const float invW = 1.f / fW;
        const int st = c_ST[lvl];

        const float* op = oa + (size_t)bq * 384 + h * 32;
        const float ox = op[idx * 2 + 0];
        const float oy = op[idx * 2 + 1];
        const float* rp = refp + (size_t)bq * 8;
        const float rx = rp[lvl * 2 + 0];
        const float ry = rp[lvl * 2 + 1];

        const float x = (rx + ox * invW) * fW - 0.5f;
        const float y = (ry + oy * invW) * fW - 0.5f;
        const float x0f = floorf(x), y0f = floorf(y);
        const int x0 = (int)x0f, y0 = (int)y0f;
        const float wx1 = x - x0f, wy1 = y - y0f;
        const float wx0 = 1.f - wx1, wy0 = 1.f - wy1;

        const float w = e * inv_se;
        const float vx0 = (x0 >= 0 && x0 < Ww) ? 1.f : 0.f;
        const float vx1 = (x0 + 1 >= 0 && x0 + 1 < Ww) ? 1.f : 0.f;
        const float vy0 = (y0 >= 0 && y0 < Ww) ? 1.f : 0.f;
        const float vy1 = (y0 + 1 >= 0 && y0 + 1 < Ww) ? 1.f : 0.f;

        cw0 = w * (wx0 * wy0) * (vx0 * vy0);
        cw1 = w * (wx1 * wy0) * (vx1 * vy0);
        cw2 = w * (wx0 * wy1) * (vx0 * vy1);
        cw3 = w * (wx1 * wy1) * (vx1 * vy1);

        const int xc0 = min(max(x0, 0), Ww - 1);
        const int xc1 = min(max(x0 + 1, 0), Ww - 1);
        const int yc0 = min(max(y0, 0), Ww - 1);
        const int yc1 = min(max(y0 + 1, 0), Ww - 1);
        ci0 = (st + yc0 * Ww + xc0) * 256;
        ci1 = (st + yc0 * Ww + xc1) * 256;
        ci2 = (st + yc1 * Ww + xc0) * 256;
        ci3 = (st + yc1 * Ww + xc1) * 256;
    }

    // ---- gather: all 32 lanes = 32 channels, fully coalesced, branch-free ----
    const float* vbase = value + (size_t)b * LQ * 256 + h * 32 + lane;
    float acc = 0.f;
#pragma unroll
    for (int p = 0; p < 16; p++) {
        const int i0 = __shfl_sync(0xffffffffu, ci0, p);
        const int i1 = __shfl_sync(0xffffffffu, ci1, p);
        const int i2 = __shfl_sync(0xffffffffu, ci2, p);
        const int i3 = __shfl_sync(0xffffffffu, ci3, p);
        const float w0 = __shfl_sync(0xffffffffu, cw0, p);
        const float w1 = __shfl_sync(0xffffffffu, cw1, p);
        const float w2 = __shfl_sync(0xffffffffu, cw2, p);
        const float w3 = __shfl_sync(0xffffffffu, cw3, p);
        const float v0 = __ldg(vbase + i0);
        const float v1 = __ldg(vbase + i1);
        const float v2 = __ldg(vbase + i2);
        const float v3 = __ldg(vbase + i3);
        acc += w0 * v0 + w1 * v1 + w2 * v2 + w3 * v3;
    }
    samp[(size_t)bq * 256 + h * 32 + lane] = rna_tf32(acc);
}

// ---------------- layernorm: one warp per row, float4 ----------------
template <bool WR32>
__global__ void __launch_bounds__(256) ln4_kernel(
    const float* __restrict__ in, const float* __restrict__ g,
    const float* __restrict__ b, float* __restrict__ out, float* __restrict__ out32)
{
    const int lane = threadIdx.x & 31;
    const size_t row = blockIdx.x * 8 + (threadIdx.x >> 5);
    const float4* in4 = (const float4*)(in + row * 256);
    const float4 A = in4[lane * 2], B4 = in4[lane * 2 + 1];

    float s = A.x + A.y + A.z + A.w + B4.x + B4.y + B4.z + B4.w;
#pragma unroll
    for (int o = 16; o; o >>= 1) s += __shfl_xor_sync(0xffffffffu, s, o);
    const float mu = s * (1.f / 256.f);

    float4 dA, dB;
    dA.x = A.x - mu; dA.y = A.y - mu; dA.z = A.z - mu; dA.w = A.w - mu;
    dB.x = B4.x - mu; dB.y = B4.y - mu; dB.z = B4.z - mu; dB.w = B4.w - mu;
    float v = dA.x*dA.x + dA.y*dA.y + dA.z*dA.z + dA.w*dA.w
            + dB.x*dB.x + dB.y*dB.y + dB.z*dB.z + dB.w*dB.w;
#pragma unroll
    for (int o = 16; o; o >>= 1) v += __shfl_xor_sync(0xffffffffu, v, o);
    const float rstd = rsqrtf(v * (1.f / 256.f) + 1e-5f);

    const float4 gA = ((const float4*)g)[lane * 2], gB = ((const float4*)g)[lane * 2 + 1];
    const float4 bA = ((const float4*)b)[lane * 2], bB = ((const float4*)b)[lane * 2 + 1];
    float4 yA, yB;
    yA.x = dA.x * rstd * gA.x + bA.x; yA.y = dA.y * rstd * gA.y + bA.y;
    yA.z = dA.z * rstd * gA.z + bA.z; yA.w = dA.w * rstd * gA.w + bA.w;
    yB.x = dB.x * rstd * gB.x + bB.x; yB.y = dB.y * rstd * gB.y + bB.y;
    yB.z = dB.z * rstd * gB.z + bB.z; yB.w = dB.w * rstd * gB.w + bB.w;

    float4* o4 = (float4*)(out + row * 256);
    o4[lane * 2] = yA; o4[lane * 2 + 1] = yB;
    if (WR32) {
        float4 rA, rB;
        rA.x = rna_tf32(yA.x); rA.y = rna_tf32(yA.y); rA.z = rna_tf32(yA.z); rA.w = rna_tf32(yA.w);
        rB.x = rna_tf32(yB.x); rB.y = rna_tf32(yB.y); rB.z = rna_tf32(yB.z); rB.w = rna_tf32(yB.w);
        float4* r4 = (float4*)(out32 + row * 256);
        r4[lane * 2] = rA; r4[lane * 2 + 1] = rB;
    }
}

// ---------------- launch ----------------
extern "C" void kernel_launch(void* const* d_in, const int* in_sizes, int n_in,
                              void* d_out, int out_size)
{
    const float* src    = (const float*)d_in[0];
    const float* pos    = (const float*)d_in[1];
    const float* refp   = (const float*)d_in[2];
    const float* W_off  = (const float*)d_in[3];
    const float* b_off  = (const float*)d_in[4];
    const float* W_attn = (const float*)d_in[5];
    const float* b_attn = (const float*)d_in[6];
    const float* W_val  = (const float*)d_in[7];
    const float* b_val  = (const float*)d_in[8];
    const float* W_out  = (const float*)d_in[9];
    const float* b_out  = (const float*)d_in[10];
    const float* ln1_g  = (const float*)d_in[11];
    const float* ln1_b  = (const float*)d_in[12];
    const float* W1     = (const float*)d_in[13];
    const float* b1     = (const float*)d_in[14];
    const float* W2     = (const float*)d_in[15];
    const float* b2     = (const float*)d_in[16];
    const float* ln2_g  = (const float*)d_in[17];
    const float* ln2_b  = (const float*)d_in[18];
    float* out = (float*)d_out;

    float *p_src32, *p_qsum, *p_value, *p_oa, *p_samp, *p_t1, *p_h, *p_h32, *p_ffn, *p_t2;
    float *p_WvalT, *p_WoaT, *p_WoutT, *p_W1T, *p_W2T;
    cudaGetSymbolAddress((void**)&p_src32, g_src32);
    cudaGetSymbolAddress((void**)&p_qsum,  g_qsum);
    cudaGetSymbolAddress((void**)&p_value, g_value);
    cudaGetSymbolAddress((void**)&p_oa,    g_oa);
    cudaGetSymbolAddress((void**)&p_samp,  g_samp);
    cudaGetSymbolAddress((void**)&p_t1,    g_t1);
    cudaGetSymbolAddress((void**)&p_h,     g_h);
    cudaGetSymbolAddress((void**)&p_h32,   g_h32);
    cudaGetSymbolAddress((void**)&p_ffn,   g_ffn);
    cudaGetSymbolAddress((void**)&p_t2,    g_t2);
    cudaGetSymbolAddress((void**)&p_WvalT, g_WvalT);
    cudaGetSymbolAddress((void**)&p_WoaT,  g_WoaT);
    cudaGetSymbolAddress((void**)&p_WoutT, g_WoutT);
    cudaGetSymbolAddress((void**)&p_W1T,   g_W1T);
    cudaGetSymbolAddress((void**)&p_W2T,   g_W2T);

    const int SMEM_BYTES = 2 * 32768;
    cudaFuncSetAttribute(gemm_mma<false, false, false>, cudaFuncAttributeMaxDynamicSharedMemorySize, SMEM_BYTES);
    cudaFuncSetAttribute(gemm_mma<true,  false, false>, cudaFuncAttributeMaxDynamicSharedMemorySize, SMEM_BYTES);
    cudaFuncSetAttribute(gemm_mma<false, true,  true >, cudaFuncAttributeMaxDynamicSharedMemorySize, SMEM_BYTES);

    const int M = M_ROWS;
    const int MT = M / 128;  // 340
    const int BIG = 1 << 30;

    {
        int n4 = M * D_MODEL / 4;
        prep_kernel<<<(n4 + 255) / 256, 256>>>(src, pos, p_src32, p_qsum, n4);
    }
    transpose_rna<<<dim3(8, 8), 256>>>(W_val,  p_WvalT, 256, 256);
    transpose_rna<<<dim3(8, 8), 256>>>(W_off,  p_WoaT,  256, 256);
    transpose_rna<<<dim3(4, 8), 256>>>(W_attn, p_WoaT + 256 * 256, 256, 128);
    transpose_rna<<<dim3(8, 8), 256>>>(W_out,  p_WoutT, 256, 256);
    transpose_rna<<<dim3(32, 8), 256>>>(W1,    p_W1T,   256, 1024);
    transpose_rna<<<dim3(8, 32), 256>>>(W2,    p_W2T,   1024, 256);

    // value = src @ W_val + b_val
    gemm_mma<false, false, false><<<dim3(2, MT), 256, SMEM_BYTES>>>(
        p_src32, p_WvalT, b_val, b_val, BIG, nullptr, p_value, 256, 256);
    // oa = (src+pos) @ [W_off|W_attn] + [b_off|b_attn]
    gemm_mma<false, false, false><<<dim3(3, MT), 256, SMEM_BYTES>>>(
        p_qsum, p_WoaT, b_off, b_attn, 256, nullptr, p_oa, 384, 256);
    // sampling
    sample_bf<<<M, 256>>>(p_value, p_oa, refp, p_samp);
    // t1 = samp @ W_out + b_out + src
    gemm_mma<true, false, false><<<dim3(2, MT), 256, SMEM_BYTES>>>(
        p_samp, p_WoutT, b_out, b_out, BIG, src, p_t1, 256, 256);
    // h = LN1(t1)
    ln4_kernel<true><<<M / 8, 256>>>(p_t1, ln1_g, ln1_b, p_h, p_h32);
    // ffn = round(relu(h @ W1 + b1))
    gemm_mma<false, true, true><<<dim3(8, MT), 256, SMEM_BYTES>>>(
        p_h32, p_W1T, b1, b1, BIG, nullptr, p_ffn, 1024, 256);
    // t2 = ffn @ W2 + b2 + h
    gemm_mma<true, false, false><<<dim3(2, MT), 256, SMEM_BYTES>>>(
        p_ffn, p_W2T, b2, b2, BIG, p_h, p_t2, 256, 1024);
    // out = LN2(t2)
    ln4_kernel<false><<<M / 8, 256>>>(p_t2, ln2_g, ln2_b, out, nullptr);
}